// round 1
// baseline (speedup 1.0000x reference)
#include <cuda_runtime.h>

#define NV 2000
#define EV 64
#define NN (NV*NV)
#define MAXZ 4096
#define ASPLIT 5          // 2000/5 = 400, divisible by 8
#define AROWS 400

// ---------------- device scratch (no allocations allowed) ----------------
__device__ float g_rp[ASPLIT][NV*EV];   // partial s3 inner sums
__device__ float g_base[NV*EV];         // s1 + s3 (loop invariant)
__device__ float g_mu[NV*EV];
__device__ float g_corr[NV*EV];         // sparse adj-zero corrections to s2
__device__ float g_v[EV];               // broadcast part of s2
__device__ float g_cpart[63][EV];       // per-block column-sum partials of mu
__device__ int   g_nz;
__device__ int2  g_zpos[MAXZ];          // (row j, col i) where W[j,i] <= 0

// ---------------- init: corr=0, v=t2b (s2 with mu=0), nz=0 ----------------
__global__ void init_kernel(const float* __restrict__ t2b) {
    int idx = blockIdx.x * 256 + threadIdx.x;
    if (idx < NV * EV) g_corr[idx] = 0.f;
    if (blockIdx.x == 0) {
        if (threadIdx.x < EV) g_v[threadIdx.x] = t2b[threadIdx.x];
        if (threadIdx.x == 0) g_nz = 0;
    }
}

// ---------------- scan W for entries <= 0 (adj zeros) ----------------
__global__ void zscan_kernel(const float* __restrict__ W) {
    int base = blockIdx.x * 256 + threadIdx.x;
    #pragma unroll
    for (int k = 0; k < 16; k++) {
        int i = base + k * (1024 * 256);
        if (i < NN && W[i] <= 0.f) {
            int p = atomicAdd(&g_nz, 1);
            if (p < MAXZ) { g_zpos[p].x = i / NV; g_zpos[p].y = i % NV; }
        }
    }
}

// ---------------- s3 inner: r[b,e] = sum_a relu(W[a,b]*w4[e] + b4[e]) ------
// grid (63, ASPLIT), 256 threads: 32 b-columns x 8 e-groups of 8.
__global__ void __launch_bounds__(256) s3_kernel(const float* __restrict__ W,
                                                 const float* __restrict__ w4,
                                                 const float* __restrict__ b4) {
    __shared__ float sW[8][32];
    int tid = threadIdx.x;
    int bl  = tid & 31;        // b within tile
    int eg  = tid >> 5;        // e group 0..7
    int b0  = blockIdx.x * 32;
    int a0  = blockIdx.y * AROWS;

    float w4r[8], b4r[8], acc[8];
    #pragma unroll
    for (int q = 0; q < 8; q++) {
        w4r[q] = w4[eg * 8 + q];
        b4r[q] = b4[eg * 8 + q];
        acc[q] = 0.f;
    }

    int lrow = tid >> 5;       // row within 8-chunk to load
    int lcol = b0 + (tid & 31);
    for (int a = a0; a < a0 + AROWS; a += 8) {
        float wv = 0.f;
        if (lcol < NV) wv = W[(a + lrow) * NV + lcol];
        sW[lrow][tid & 31] = wv;
        __syncthreads();
        #pragma unroll
        for (int aa = 0; aa < 8; aa++) {
            float w = sW[aa][bl];
            #pragma unroll
            for (int q = 0; q < 8; q++)
                acc[q] += fmaxf(fmaf(w, w4r[q], b4r[q]), 0.f);
        }
        __syncthreads();
    }

    int b = b0 + bl;
    if (b < NV) {
        #pragma unroll
        for (int q = 0; q < 8; q++)
            g_rp[blockIdx.y][b * EV + eg * 8 + q] = acc[q];
    }
}

// ---------------- base = xv@t1w + t1b + r@t3w + t3b ----------------
__global__ void __launch_bounds__(256) base_kernel(const float* __restrict__ xv,
                                                   const float* __restrict__ t1w,
                                                   const float* __restrict__ t1b,
                                                   const float* __restrict__ t3w,
                                                   const float* __restrict__ t3b) {
    __shared__ float s1w[EV * EV];
    __shared__ float s3w[EV * EV];
    __shared__ float sx[32][EV];
    __shared__ float sr[32][EV];
    int tid = threadIdx.x;
    for (int i = tid; i < EV * EV; i += 256) { s1w[i] = t1w[i]; s3w[i] = t3w[i]; }
    int j0 = blockIdx.x * 32;
    for (int i = tid; i < 32 * EV; i += 256) {
        int jj = i >> 6, e = i & 63;
        int j = j0 + jj;
        float x = 0.f, r = 0.f;
        if (j < NV) {
            x = xv[j * EV + e];
            #pragma unroll
            for (int p = 0; p < ASPLIT; p++) r += g_rp[p][j * EV + e];
        }
        sx[jj][e] = x; sr[jj][e] = r;
    }
    __syncthreads();
    int e = tid & 63;
    int grp = tid >> 6;
    #pragma unroll
    for (int p = 0; p < 8; p++) {
        int jj = grp * 8 + p;
        float acc = t1b[e] + t3b[e];
        #pragma unroll
        for (int k = 0; k < EV; k++)
            acc += sx[jj][k] * s1w[k * EV + e] + sr[jj][k] * s3w[k * EV + e];
        int j = j0 + jj;
        if (j < NV) g_base[j * EV + e] = acc;
    }
}

// ---------------- mu = relu(base + v - corr), column-sum partials ----------
__global__ void __launch_bounds__(256) mu_kernel() {
    __shared__ float sc[4][EV];
    int tid = threadIdx.x;
    int e = tid & 63;
    int grp = tid >> 6;           // 0..3
    int j0 = blockIdx.x * 32;
    float v = g_v[e];
    float csum = 0.f;
    #pragma unroll
    for (int p = 0; p < 8; p++) {
        int j = j0 + grp * 8 + p;
        if (j < NV) {
            float m = fmaxf(g_base[j * EV + e] + v - g_corr[j * EV + e], 0.f);
            g_mu[j * EV + e] = m;
            csum += m;
        }
    }
    sc[grp][e] = csum;
    __syncthreads();
    if (grp == 0)
        g_cpart[blockIdx.x][e] = sc[0][e] + sc[1][e] + sc[2][e] + sc[3][e];
}

// ---------------- prep: v = c@t2w + t2b ; zero corr if any adj-zeros -------
__global__ void prep_kernel(const float* __restrict__ t2w,
                            const float* __restrict__ t2b) {
    if (blockIdx.x == 0) {
        __shared__ float sc[EV];
        int tid = threadIdx.x;
        if (tid < EV) {
            float c = 0.f;
            for (int b = 0; b < 63; b++) c += g_cpart[b][tid];
            sc[tid] = c;
        }
        __syncthreads();
        if (tid < EV) {
            float acc = t2b[tid];
            #pragma unroll
            for (int k = 0; k < EV; k++) acc += sc[k] * t2w[k * EV + tid];
            g_v[tid] = acc;
        }
    } else {
        if (g_nz == 0) return;
        int idx = (blockIdx.x - 1) * 256 + threadIdx.x;
        if (idx < NV * EV) g_corr[idx] = 0.f;
    }
}

// ---------------- apply sparse corrections: corr[j] += mu[i]@t2w -----------
__global__ void apply_kernel(const float* __restrict__ t2w) {
    int nz = g_nz;
    if (nz == 0) return;
    if (nz > MAXZ) nz = MAXZ;
    int e = threadIdx.x;   // blockDim = 64
    for (int z = blockIdx.x; z < nz; z += gridDim.x) {
        int2 p = g_zpos[z];
        float acc = 0.f;
        #pragma unroll
        for (int k = 0; k < EV; k++) acc += g_mu[p.y * EV + k] * t2w[k * EV + e];
        atomicAdd(&g_corr[p.x * EV + e], acc);
    }
}

// ---------------- final head ----------------
__global__ void __launch_bounds__(256) final_kernel(const float* __restrict__ t5w,
                                                    const float* __restrict__ t5b,
                                                    const float* __restrict__ t6w,
                                                    const float* __restrict__ t6b,
                                                    const float* __restrict__ t7w,
                                                    const float* __restrict__ t7b,
                                                    float* __restrict__ out) {
    __shared__ float s7w[EV * EV];
    __shared__ float sc[EV];
    __shared__ float smu[32][EV];
    __shared__ float sred[EV];
    __shared__ float swsum[8][8];
    __shared__ float sgg;
    int tid = threadIdx.x;

    if (tid < EV) {
        float c = 0.f;
        for (int b = 0; b < 63; b++) c += g_cpart[b][tid];
        sc[tid] = c;
    }
    for (int i = tid; i < EV * EV; i += 256) s7w[i] = t7w[i];
    int j0 = blockIdx.x * 32;
    for (int i = tid; i < 32 * EV; i += 256) {
        int jj = i >> 6, e = i & 63;
        int j = j0 + jj;
        smu[jj][e] = (j < NV) ? g_mu[j * EV + e] : 0.f;
    }
    __syncthreads();

    if (tid < EV) {
        float acc = t6b[tid];
        #pragma unroll
        for (int k = 0; k < EV; k++) acc += sc[k] * t6w[k * EV + tid];
        sred[tid] = fmaxf(acc, 0.f) * t5w[tid];
    }
    __syncthreads();
    if (tid == 0) {
        float gg = 0.f;
        #pragma unroll
        for (int k = 0; k < EV; k++) gg += sred[k];
        sgg = gg;
    }
    __syncthreads();

    int e = tid & 63;
    int grp = tid >> 6;     // 0..3 ; warps 2*grp, 2*grp+1 cover e 0..63
    float red[8];
    #pragma unroll
    for (int p = 0; p < 8; p++) {
        int jj = grp * 8 + p;
        float acc = t7b[e];
        #pragma unroll
        for (int k = 0; k < EV; k++) acc = fmaf(smu[jj][k], s7w[k * EV + e], acc);
        float val = fmaxf(acc, 0.f) * t5w[EV + e];
        #pragma unroll
        for (int off = 16; off; off >>= 1)
            val += __shfl_xor_sync(0xffffffffu, val, off);
        red[p] = val;
    }
    int warp = tid >> 5, lane = tid & 31;
    if (lane == 0) {
        #pragma unroll
        for (int p = 0; p < 8; p++) swsum[warp][p] = red[p];
    }
    __syncthreads();
    if (tid < 32) {
        int g2 = tid >> 3, p = tid & 7;
        int j = j0 + g2 * 8 + p;
        if (j < NV)
            out[j] = sgg + t5b[0] + swsum[2 * g2][p] + swsum[2 * g2 + 1][p];
    }
}

// ---------------- host launch ----------------
extern "C" void kernel_launch(void* const* d_in, const int* in_sizes, int n_in,
                              void* d_out, int out_size) {
    const float* xv  = (const float*)d_in[0];
    const float* W   = (const float*)d_in[1];
    const float* t1w = (const float*)d_in[2];
    const float* t1b = (const float*)d_in[3];
    const float* t2w = (const float*)d_in[4];
    const float* t2b = (const float*)d_in[5];
    const float* t3w = (const float*)d_in[6];
    const float* t3b = (const float*)d_in[7];
    const float* t4w = (const float*)d_in[8];
    const float* t4b = (const float*)d_in[9];
    const float* t5w = (const float*)d_in[10];
    const float* t5b = (const float*)d_in[11];
    const float* t6w = (const float*)d_in[12];
    const float* t6b = (const float*)d_in[13];
    const float* t7w = (const float*)d_in[14];
    const float* t7b = (const float*)d_in[15];
    float* out = (float*)d_out;

    init_kernel<<<512, 256>>>(t2b);
    zscan_kernel<<<1024, 256>>>(W);
    s3_kernel<<<dim3(63, ASPLIT), 256>>>(W, t4w, t4b);
    base_kernel<<<63, 256>>>(xv, t1w, t1b, t3w, t3b);
    for (int t = 0; t < 4; t++) {
        mu_kernel<<<63, 256>>>();
        if (t < 3) {
            prep_kernel<<<512, 256>>>(t2w, t2b);
            apply_kernel<<<64, 64>>>(t2w);
        }
    }
    final_kernel<<<63, 256>>>(t5w, t5b, t6w, t6b, t7w, t7b, out);
}

// round 3
// speedup vs baseline: 1.0766x; 1.0766x over previous
#include <cuda_runtime.h>

#define NV 2000
#define EV 64
#define MAXZ 4096

typedef unsigned long long u64;

// ---------------- device scratch ----------------
__device__ float g_base[NV * EV];          // s1 + s3 (loop invariant)
__device__ float g_mu[2][NV * EV];         // double-buffered mu
__device__ float g_cpart[2][250][EV];      // per-block column-sum partials of mu
__device__ int   g_nz;
__device__ int   g_rowflag[NV];            // row j has a W[j,*] <= 0 entry
__device__ int2  g_zpos[MAXZ];             // (row j, col i) where W[j,i] <= 0

// ---------------- packed f32x2 helpers ----------------
__device__ __forceinline__ u64 fma2(u64 a, u64 b, u64 c) {
    u64 d;
    asm("fma.rn.f32x2 %0, %1, %2, %3;" : "=l"(d) : "l"(a), "l"(b), "l"(c));
    return d;
}
__device__ __forceinline__ u64 add2(u64 a, u64 b) {
    u64 d;
    asm("add.rn.f32x2 %0, %1, %2;" : "=l"(d) : "l"(a), "l"(b));
    return d;
}
__device__ __forceinline__ u64 pack2(float lo, float hi) {
    u64 r;
    asm("mov.b64 %0, {%1, %2};" : "=l"(r) : "f"(lo), "f"(hi));
    return r;
}
__device__ __forceinline__ void unpack2(u64 v, float& lo, float& hi) {
    asm("mov.b64 {%0, %1}, %2;" : "=f"(lo), "=f"(hi) : "l"(v));
}
__device__ __forceinline__ u64 relu2(u64 y) {
    float lo, hi;
    unpack2(y, lo, hi);
    lo = fmaxf(lo, 0.f);
    hi = fmaxf(hi, 0.f);
    return pack2(lo, hi);
}

// ---------------- setup: g_base = xv@t1w + t1b + t3b; zero flags ----------
__global__ void __launch_bounds__(256) setup_kernel(const float* __restrict__ xv,
                                                    const float* __restrict__ t1w,
                                                    const float* __restrict__ t1b,
                                                    const float* __restrict__ t3b) {
    __shared__ float s1w[EV * EV];
    __shared__ float sx[8][EV];
    int tid = threadIdx.x;
    int j0 = blockIdx.x * 8;
    for (int i = tid; i < EV * EV; i += 256) s1w[i] = t1w[i];
    for (int i = tid; i < 8 * EV; i += 256) {
        int jj = i >> 6, k = i & 63;
        sx[jj][k] = xv[(j0 + jj) * EV + k];
    }
    if (tid < 8) g_rowflag[j0 + tid] = 0;
    if (blockIdx.x == 0 && tid == 0) g_nz = 0;
    __syncthreads();
    int e = tid & 63;
    int grp = tid >> 6;
    #pragma unroll
    for (int p = 0; p < 2; p++) {
        int jj = grp * 2 + p;
        float acc = t1b[e] + t3b[e];
        #pragma unroll
        for (int k = 0; k < EV; k++)
            acc = fmaf(sx[jj][k], s1w[k * EV + e], acc);
        g_base[(j0 + jj) * EV + e] = acc;
    }
}

// ---------------- s3: r[b,e] = sum_a relu(W[a,b]*w4[e]+b4[e]);
//                  then g_base += r_partial @ t3w ; also detect adj zeros ----
// grid (63 b-tiles, 4 a-splits of 500 rows), 256 thr = 32 cols x 8 e-groups
__global__ void __launch_bounds__(256) s3_kernel(const float* __restrict__ W,
                                                 const float* __restrict__ w4,
                                                 const float* __restrict__ b4,
                                                 const float* __restrict__ t3w) {
    __shared__ float sW[8][32];
    __shared__ float sR[32][EV + 1];
    __shared__ float s3w[EV * EV];
    int tid = threadIdx.x;
    int bl  = tid & 31;
    int eg  = tid >> 5;
    int b0  = blockIdx.x * 32;
    int a0  = blockIdx.y * 500;
    int a1  = a0 + 500;

    u64 w4p[4], b4p[4], acc[4];
    #pragma unroll
    for (int q = 0; q < 4; q++) {
        int e = eg * 8 + 2 * q;
        w4p[q] = pack2(w4[e], w4[e + 1]);
        b4p[q] = pack2(b4[e], b4[e + 1]);
        acc[q] = 0ull;
    }

    int lrow = tid >> 5;
    int lcol = b0 + bl;
    bool colok = (lcol < NV);

    int a = a0;
    for (; a + 8 <= a1; a += 8) {
        float wv = 0.f;
        if (colok) {
            wv = W[(a + lrow) * NV + lcol];
            if (wv <= 0.f) {
                int p = atomicAdd(&g_nz, 1);
                if (p < MAXZ) {
                    g_zpos[p].x = a + lrow;   // j (adj row)
                    g_zpos[p].y = lcol;       // i (adj col)
                    g_rowflag[a + lrow] = 1;
                }
            }
        }
        sW[lrow][bl] = wv;
        __syncthreads();
        #pragma unroll
        for (int aa = 0; aa < 8; aa++) {
            float w = sW[aa][bl];
            u64 ww = pack2(w, w);
            #pragma unroll
            for (int q = 0; q < 4; q++)
                acc[q] = add2(acc[q], relu2(fma2(ww, w4p[q], b4p[q])));
        }
        __syncthreads();
    }
    // tail (500 = 62*8 + 4)
    if (a < a1) {
        float wv = 0.f;
        if (colok && (a + lrow) < a1) {
            wv = W[(a + lrow) * NV + lcol];
            if (wv <= 0.f) {
                int p = atomicAdd(&g_nz, 1);
                if (p < MAXZ) {
                    g_zpos[p].x = a + lrow;
                    g_zpos[p].y = lcol;
                    g_rowflag[a + lrow] = 1;
                }
            }
        }
        sW[lrow][bl] = wv;
        __syncthreads();
        int nt = a1 - a;
        for (int aa = 0; aa < nt; aa++) {
            float w = sW[aa][bl];
            u64 ww = pack2(w, w);
            #pragma unroll
            for (int q = 0; q < 4; q++)
                acc[q] = add2(acc[q], relu2(fma2(ww, w4p[q], b4p[q])));
        }
        __syncthreads();
    }

    // stash partial r into shared
    #pragma unroll
    for (int q = 0; q < 4; q++) {
        float lo, hi;
        unpack2(acc[q], lo, hi);
        sR[bl][eg * 8 + 2 * q]     = lo;
        sR[bl][eg * 8 + 2 * q + 1] = hi;
    }
    for (int i = tid; i < EV * EV; i += 256) s3w[i] = t3w[i];
    __syncthreads();

    // epilogue: g_base[b, f] += sum_k r[b,k] * t3w[k,f]
    int f = tid & 63;
    int grp = tid >> 6;
    #pragma unroll
    for (int p = 0; p < 8; p++) {
        int cr = grp * 8 + p;
        float s = 0.f;
        #pragma unroll
        for (int k = 0; k < EV; k++)
            s = fmaf(sR[cr][k], s3w[k * EV + f], s);
        int b = b0 + cr;
        if (b < NV) atomicAdd(&g_base[b * EV + f], s);
    }
}

// ---------------- mu iteration: mu_t = relu(base + v - corr) ----------------
// grid 250 x 8 rows. v recomputed per block from cpart[t-1]. corr inline
// from sparse adj-zero list (reads mu buffer t-1, writes buffer t).
__global__ void __launch_bounds__(256) mu_kernel(const float* __restrict__ t2w,
                                                 const float* __restrict__ t2b,
                                                 int t) {
    __shared__ float st2w[EV * EV];
    __shared__ float sc4[4][EV];
    __shared__ float scs[EV];
    __shared__ float sv[EV];
    __shared__ float scp[4][EV];
    int tid = threadIdx.x;
    int e = tid & 63;
    int q = tid >> 6;
    int j0 = blockIdx.x * 8;
    int prev = (t - 1) & 1;

    for (int i = tid; i < EV * EV; i += 256) st2w[i] = t2w[i];

    if (t == 0) {
        if (tid < EV) sv[tid] = t2b[tid];
        __syncthreads();
    } else {
        int start = q * 63;
        int end   = (q == 3) ? 250 : start + 63;
        float s = 0.f;
        for (int b = start; b < end; b++) s += g_cpart[prev][b][e];
        sc4[q][e] = s;
        __syncthreads();
        if (tid < EV) scs[tid] = sc4[0][tid] + sc4[1][tid] + sc4[2][tid] + sc4[3][tid];
        __syncthreads();
        if (tid < EV) {
            float a = t2b[tid];
            #pragma unroll
            for (int k = 0; k < EV; k++)
                a = fmaf(scs[k], st2w[k * EV + tid], a);
            sv[tid] = a;
        }
        __syncthreads();
    }

    int nz = g_nz;
    if (nz > MAXZ) nz = MAXZ;
    float v = sv[e];
    float csum = 0.f;
    #pragma unroll
    for (int p = 0; p < 2; p++) {
        int j = j0 + q * 2 + p;
        float corr = 0.f;
        if (nz > 0 && t > 0 && g_rowflag[j]) {
            for (int z = 0; z < nz; z++) {
                int2 zp = g_zpos[z];
                if (zp.x == j) {
                    float a2 = 0.f;
                    for (int k = 0; k < EV; k++)
                        a2 = fmaf(g_mu[prev][zp.y * EV + k], st2w[k * EV + e], a2);
                    corr += a2;
                }
            }
        }
        float m = fmaxf(g_base[j * EV + e] + v - corr, 0.f);
        g_mu[t & 1][j * EV + e] = m;
        csum += m;
    }
    scp[q][e] = csum;
    __syncthreads();
    if (q == 0)
        g_cpart[t & 1][blockIdx.x][e] = scp[0][e] + scp[1][e] + scp[2][e] + scp[3][e];
}

// ---------------- final head ----------------
__global__ void __launch_bounds__(256) final_kernel(const float* __restrict__ t5w,
                                                    const float* __restrict__ t5b,
                                                    const float* __restrict__ t6w,
                                                    const float* __restrict__ t6b,
                                                    const float* __restrict__ t7w,
                                                    const float* __restrict__ t7b,
                                                    float* __restrict__ out) {
    __shared__ float s7w[EV * EV];
    __shared__ float sc4[4][EV];
    __shared__ float scs[EV];
    __shared__ float sgv[EV];
    __shared__ float smu[8][EV];
    __shared__ float swsum[8][2];
    __shared__ float sgg;
    int tid = threadIdx.x;
    int e = tid & 63;
    int q = tid >> 6;
    int j0 = blockIdx.x * 8;

    for (int i = tid; i < EV * EV; i += 256) s7w[i] = t7w[i];
    for (int i = tid; i < 8 * EV; i += 256) {
        int jj = i >> 6, k = i & 63;
        smu[jj][k] = g_mu[1][(j0 + jj) * EV + k];  // t=3 -> buffer 1
    }
    {
        int start = q * 63;
        int end   = (q == 3) ? 250 : start + 63;
        float s = 0.f;
        for (int b = start; b < end; b++) s += g_cpart[1][b][e];
        sc4[q][e] = s;
    }
    __syncthreads();
    if (tid < EV) scs[tid] = sc4[0][tid] + sc4[1][tid] + sc4[2][tid] + sc4[3][tid];
    __syncthreads();
    if (tid < EV) {
        float a = t6b[tid];
        #pragma unroll
        for (int k = 0; k < EV; k++)
            a = fmaf(scs[k], t6w[k * EV + tid], a);
        sgv[tid] = fmaxf(a, 0.f) * t5w[tid];
    }
    __syncthreads();
    if (tid == 0) {
        float gg = 0.f;
        #pragma unroll
        for (int k = 0; k < EV; k++) gg += sgv[k];
        sgg = gg;
    }
    __syncthreads();

    float red[2];
    #pragma unroll
    for (int p = 0; p < 2; p++) {
        int jj = q * 2 + p;
        float acc = t7b[e];
        #pragma unroll
        for (int k = 0; k < EV; k++)
            acc = fmaf(smu[jj][k], s7w[k * EV + e], acc);
        float val = fmaxf(acc, 0.f) * t5w[EV + e];
        #pragma unroll
        for (int off = 16; off; off >>= 1)
            val += __shfl_xor_sync(0xffffffffu, val, off);
        red[p] = val;
    }
    int warp = tid >> 5, lane = tid & 31;
    if (lane == 0) {
        swsum[warp][0] = red[0];
        swsum[warp][1] = red[1];
    }
    __syncthreads();
    if (tid < 8) {
        int qq = tid >> 1, p = tid & 1;
        out[j0 + tid] = sgg + t5b[0] + swsum[2 * qq][p] + swsum[2 * qq + 1][p];
    }
}

// ---------------- host launch ----------------
extern "C" void kernel_launch(void* const* d_in, const int* in_sizes, int n_in,
                              void* d_out, int out_size) {
    const float* xv  = (const float*)d_in[0];
    const float* W   = (const float*)d_in[1];
    const float* t1w = (const float*)d_in[2];
    const float* t1b = (const float*)d_in[3];
    const float* t2w = (const float*)d_in[4];
    const float* t2b = (const float*)d_in[5];
    const float* t3w = (const float*)d_in[6];
    const float* t3b = (const float*)d_in[7];
    const float* t4w = (const float*)d_in[8];
    const float* t4b = (const float*)d_in[9];
    const float* t5w = (const float*)d_in[10];
    const float* t5b = (const float*)d_in[11];
    const float* t6w = (const float*)d_in[12];
    const float* t6b = (const float*)d_in[13];
    const float* t7w = (const float*)d_in[14];
    const float* t7b = (const float*)d_in[15];
    float* out = (float*)d_out;

    setup_kernel<<<250, 256>>>(xv, t1w, t1b, t3b);
    s3_kernel<<<dim3(63, 4), 256>>>(W, t4w, t4b, t3w);
    for (int t = 0; t < 4; t++)
        mu_kernel<<<250, 256>>>(t2w, t2b, t);
    final_kernel<<<250, 256>>>(t5w, t5b, t6w, t6b, t7w, t7b, out);
}

// round 5
// speedup vs baseline: 1.2170x; 1.1304x over previous
#include <cuda_runtime.h>

#define NV 2000
#define EV 64
#define MAXZ 4096

typedef unsigned long long u64;

// ---------------- device scratch ----------------
__device__ float g_base[NV * EV];          // s1 + s3 (loop invariant)
__device__ float g_mu[2][NV * EV];         // double-buffered mu
__device__ float g_csum[4][EV];            // column sums of mu_t (atomic accum)
__device__ float g_v[EV];                  // broadcast part of s2 for current iter
__device__ int   g_nz;
__device__ int   g_rowflag[NV];            // row j has a W[j,*] <= 0 entry
__device__ int2  g_zpos[MAXZ];             // (row j, col i) where W[j,i] <= 0

// ---------------- packed f32x2 helpers ----------------
__device__ __forceinline__ u64 fma2(u64 a, u64 b, u64 c) {
    u64 d;
    asm("fma.rn.f32x2 %0, %1, %2, %3;" : "=l"(d) : "l"(a), "l"(b), "l"(c));
    return d;
}
__device__ __forceinline__ u64 add2(u64 a, u64 b) {
    u64 d;
    asm("add.rn.f32x2 %0, %1, %2;" : "=l"(d) : "l"(a), "l"(b));
    return d;
}
__device__ __forceinline__ u64 pack2(float lo, float hi) {
    u64 r;
    asm("mov.b64 %0, {%1, %2};" : "=l"(r) : "f"(lo), "f"(hi));
    return r;
}
__device__ __forceinline__ void unpack2(u64 v, float& lo, float& hi) {
    asm("mov.b64 {%0, %1}, %2;" : "=f"(lo), "=f"(hi) : "l"(v));
}
__device__ __forceinline__ u64 relu2(u64 y) {
    float lo, hi;
    unpack2(y, lo, hi);
    lo = fmaxf(lo, 0.f);
    hi = fmaxf(hi, 0.f);
    return pack2(lo, hi);
}

// ---------------- setup: g_base = xv@t1w + t1b + t3b; init v, csum, flags --
__global__ void __launch_bounds__(256) setup_kernel(const float* __restrict__ xv,
                                                    const float* __restrict__ t1w,
                                                    const float* __restrict__ t1b,
                                                    const float* __restrict__ t3b,
                                                    const float* __restrict__ t2b) {
    __shared__ float s1w[EV * EV];
    __shared__ float sx[8][EV];
    int tid = threadIdx.x;
    int j0 = blockIdx.x * 8;
    for (int i = tid; i < EV * EV; i += 256) s1w[i] = t1w[i];
    for (int i = tid; i < 8 * EV; i += 256) {
        int jj = i >> 6, k = i & 63;
        sx[jj][k] = xv[(j0 + jj) * EV + k];
    }
    if (tid < 8) g_rowflag[j0 + tid] = 0;
    if (blockIdx.x == 0) {
        if (tid == 0) g_nz = 0;
        if (tid < 4 * EV) g_csum[tid >> 6][tid & 63] = 0.f;
        if (tid < EV) g_v[tid] = t2b[tid];   // v for iteration 0 (mu_-1 = 0)
    }
    __syncthreads();
    int e = tid & 63;
    int grp = tid >> 6;
    #pragma unroll
    for (int p = 0; p < 2; p++) {
        int jj = grp * 2 + p;
        float acc = t1b[e] + t3b[e];
        #pragma unroll
        for (int k = 0; k < EV; k++)
            acc = fmaf(sx[jj][k], s1w[k * EV + e], acc);
        g_base[(j0 + jj) * EV + e] = acc;
    }
}

// ---------------- s3: r[b,e] = sum_a relu(W[a,b]*w4[e]+b4[e]);
//                  then g_base += r_partial @ t3w ; also detect adj zeros ----
// grid (63 b-tiles, 4 a-splits of 500 rows), 256 thr = 32 cols x 8 e-groups
__global__ void __launch_bounds__(256) s3_kernel(const float* __restrict__ W,
                                                 const float* __restrict__ w4,
                                                 const float* __restrict__ b4,
                                                 const float* __restrict__ t3w) {
    __shared__ float sW[8][32];
    __shared__ float sR[32][EV + 1];
    __shared__ float s3w[EV * EV];
    int tid = threadIdx.x;
    int bl  = tid & 31;
    int eg  = tid >> 5;
    int b0  = blockIdx.x * 32;
    int a0  = blockIdx.y * 500;
    int a1  = a0 + 500;

    u64 w4p[4], b4p[4], acc[4];
    #pragma unroll
    for (int q = 0; q < 4; q++) {
        int e = eg * 8 + 2 * q;
        w4p[q] = pack2(w4[e], w4[e + 1]);
        b4p[q] = pack2(b4[e], b4[e + 1]);
        acc[q] = 0ull;
    }

    int lrow = tid >> 5;
    int lcol = b0 + bl;
    bool colok = (lcol < NV);

    int a = a0;
    for (; a + 8 <= a1; a += 8) {
        float wv = 0.f;
        if (colok) {
            wv = W[(a + lrow) * NV + lcol];
            if (wv <= 0.f) {
                int p = atomicAdd(&g_nz, 1);
                if (p < MAXZ) {
                    g_zpos[p].x = a + lrow;   // j (adj row)
                    g_zpos[p].y = lcol;       // i (adj col)
                    g_rowflag[a + lrow] = 1;
                }
            }
        }
        sW[lrow][bl] = wv;
        __syncthreads();
        #pragma unroll
        for (int aa = 0; aa < 8; aa++) {
            float w = sW[aa][bl];
            u64 ww = pack2(w, w);
            #pragma unroll
            for (int q = 0; q < 4; q++)
                acc[q] = add2(acc[q], relu2(fma2(ww, w4p[q], b4p[q])));
        }
        __syncthreads();
    }
    // tail (500 = 62*8 + 4)
    if (a < a1) {
        float wv = 0.f;
        if (colok && (a + lrow) < a1) {
            wv = W[(a + lrow) * NV + lcol];
            if (wv <= 0.f) {
                int p = atomicAdd(&g_nz, 1);
                if (p < MAXZ) {
                    g_zpos[p].x = a + lrow;
                    g_zpos[p].y = lcol;
                    g_rowflag[a + lrow] = 1;
                }
            }
        }
        sW[lrow][bl] = wv;
        __syncthreads();
        int nt = a1 - a;
        for (int aa = 0; aa < nt; aa++) {
            float w = sW[aa][bl];
            u64 ww = pack2(w, w);
            #pragma unroll
            for (int q = 0; q < 4; q++)
                acc[q] = add2(acc[q], relu2(fma2(ww, w4p[q], b4p[q])));
        }
        __syncthreads();
    }

    // stash partial r into shared
    #pragma unroll
    for (int q = 0; q < 4; q++) {
        float lo, hi;
        unpack2(acc[q], lo, hi);
        sR[bl][eg * 8 + 2 * q]     = lo;
        sR[bl][eg * 8 + 2 * q + 1] = hi;
    }
    for (int i = tid; i < EV * EV; i += 256) s3w[i] = t3w[i];
    __syncthreads();

    // epilogue: g_base[b, f] += sum_k r[b,k] * t3w[k,f]
    int f = tid & 63;
    int grp = tid >> 6;
    #pragma unroll
    for (int p = 0; p < 8; p++) {
        int cr = grp * 8 + p;
        float s = 0.f;
        #pragma unroll
        for (int k = 0; k < EV; k++)
            s = fmaf(sR[cr][k], s3w[k * EV + f], s);
        int b = b0 + cr;
        if (b < NV) atomicAdd(&g_base[b * EV + f], s);
    }
}

// ---------------- mu iteration: mu_t = relu(base + v - corr) ----------------
// grid 250 x 8 rows. Reads precomputed g_v; accumulates column sums into
// g_csum[t] via atomics. corr inline from sparse adj-zero list.
__global__ void __launch_bounds__(256) mu_kernel(const float* __restrict__ t2w,
                                                 int t) {
    __shared__ float scp[4][EV];
    int tid = threadIdx.x;
    int e = tid & 63;
    int q = tid >> 6;
    int j0 = blockIdx.x * 8;
    int prev = (t - 1) & 1;

    int nz = g_nz;
    if (nz > MAXZ) nz = MAXZ;
    float v = g_v[e];
    float csum = 0.f;
    #pragma unroll
    for (int p = 0; p < 2; p++) {
        int j = j0 + q * 2 + p;
        float corr = 0.f;
        if (nz > 0 && t > 0 && g_rowflag[j]) {
            for (int z = 0; z < nz; z++) {
                int2 zp = g_zpos[z];
                if (zp.x == j) {
                    float a2 = 0.f;
                    for (int k = 0; k < EV; k++)
                        a2 = fmaf(g_mu[prev][zp.y * EV + k], t2w[k * EV + e], a2);
                    corr += a2;
                }
            }
        }
        float m = fmaxf(g_base[j * EV + e] + v - corr, 0.f);
        g_mu[t & 1][j * EV + e] = m;
        csum += m;
    }
    scp[q][e] = csum;
    __syncthreads();
    if (q == 0)
        atomicAdd(&g_csum[t][e], scp[0][e] + scp[1][e] + scp[2][e] + scp[3][e]);
}

// ---------------- v update: g_v = csum[t] @ t2w + t2b ----------------
__global__ void __launch_bounds__(256) v_kernel(const float* __restrict__ t2w,
                                                const float* __restrict__ t2b,
                                                int t) {
    __shared__ float sc[EV];
    __shared__ float part[4][EV];
    int tid = threadIdx.x;
    int e = tid & 63;
    int q = tid >> 6;
    if (tid < EV) sc[tid] = g_csum[t][tid];
    __syncthreads();
    float a = 0.f;
    #pragma unroll
    for (int k = 0; k < 16; k++) {
        int kk = q * 16 + k;
        a = fmaf(sc[kk], t2w[kk * EV + e], a);
    }
    part[q][e] = a;
    __syncthreads();
    if (tid < EV)
        g_v[tid] = part[0][tid] + part[1][tid] + part[2][tid] + part[3][tid] + t2b[tid];
}

// ---------------- final head ----------------
__global__ void __launch_bounds__(256) final_kernel(const float* __restrict__ t5w,
                                                    const float* __restrict__ t5b,
                                                    const float* __restrict__ t6w,
                                                    const float* __restrict__ t6b,
                                                    const float* __restrict__ t7w,
                                                    const float* __restrict__ t7b,
                                                    float* __restrict__ out) {
    __shared__ float s7w[EV * EV];
    __shared__ float scs[EV];
    __shared__ float sgv[EV];
    __shared__ float smu[8][EV];
    __shared__ float swsum[8][2];
    __shared__ float sgg;
    int tid = threadIdx.x;
    int e = tid & 63;
    int q = tid >> 6;
    int j0 = blockIdx.x * 8;

    for (int i = tid; i < EV * EV; i += 256) s7w[i] = t7w[i];
    for (int i = tid; i < 8 * EV; i += 256) {
        int jj = i >> 6, k = i & 63;
        smu[jj][k] = g_mu[1][(j0 + jj) * EV + k];  // t=3 -> buffer 1
    }
    if (tid < EV) scs[tid] = g_csum[3][tid];
    __syncthreads();
    if (tid < EV) {
        float a = t6b[tid];
        #pragma unroll
        for (int k = 0; k < EV; k++)
            a = fmaf(scs[k], t6w[k * EV + tid], a);
        sgv[tid] = fmaxf(a, 0.f) * t5w[tid];
    }
    __syncthreads();
    if (tid == 0) {
        float gg = 0.f;
        #pragma unroll
        for (int k = 0; k < EV; k++) gg += sgv[k];
        sgg = gg;
    }
    __syncthreads();

    float red[2];
    #pragma unroll
    for (int p = 0; p < 2; p++) {
        int jj = q * 2 + p;
        float acc = t7b[e];
        #pragma unroll
        for (int k = 0; k < EV; k++)
            acc = fmaf(smu[jj][k], s7w[k * EV + e], acc);
        float val = fmaxf(acc, 0.f) * t5w[EV + e];
        #pragma unroll
        for (int off = 16; off; off >>= 1)
            val += __shfl_xor_sync(0xffffffffu, val, off);
        red[p] = val;
    }
    int warp = tid >> 5, lane = tid & 31;
    if (lane == 0) {
        swsum[warp][0] = red[0];
        swsum[warp][1] = red[1];
    }
    __syncthreads();
    if (tid < 8) {
        int qq = tid >> 1, p = tid & 1;
        out[j0 + tid] = sgg + t5b[0] + swsum[2 * qq][p] + swsum[2 * qq + 1][p];
    }
}

// ---------------- host launch ----------------
extern "C" void kernel_launch(void* const* d_in, const int* in_sizes, int n_in,
                              void* d_out, int out_size) {
    const float* xv  = (const float*)d_in[0];
    const float* W   = (const float*)d_in[1];
    const float* t1w = (const float*)d_in[2];
    const float* t1b = (const float*)d_in[3];
    const float* t2w = (const float*)d_in[4];
    const float* t2b = (const float*)d_in[5];
    const float* t3w = (const float*)d_in[6];
    const float* t3b = (const float*)d_in[7];
    const float* t4w = (const float*)d_in[8];
    const float* t4b = (const float*)d_in[9];
    const float* t5w = (const float*)d_in[10];
    const float* t5b = (const float*)d_in[11];
    const float* t6w = (const float*)d_in[12];
    const float* t6b = (const float*)d_in[13];
    const float* t7w = (const float*)d_in[14];
    const float* t7b = (const float*)d_in[15];
    float* out = (float*)d_out;

    setup_kernel<<<250, 256>>>(xv, t1w, t1b, t3b, t2b);
    s3_kernel<<<dim3(63, 4), 256>>>(W, t4w, t4b, t3w);
    for (int t = 0; t < 4; t++) {
        mu_kernel<<<250, 256>>>(t2w, t);
        if (t < 3) v_kernel<<<1, 256>>>(t2w, t2b, t);
    }
    final_kernel<<<250, 256>>>(t5w, t5b, t6w, t6b, t7w, t7b, out);
}

// round 7
// speedup vs baseline: 1.2384x; 1.0176x over previous
#include <cuda_runtime.h>

#define NV 2000
#define EV 64
#define MAXZ 4096
#define NB 252            // 63 * 4 persistent blocks

typedef unsigned long long u64;

// ---------------- device scratch ----------------
__device__ float g_base[NV * EV];          // s1 + s3 (loop invariant)
__device__ float g_mu[2][NV * EV];         // double-buffered mu
__device__ float g_csum2[4][EV][8];        // column sums of mu_t, 8-way split
__device__ int   g_nz;
__device__ int   g_rowflag[NV];            // row j has a W[j,*] <= 0 entry
__device__ int2  g_zpos[MAXZ];             // (row j, col i) where W[j,i] <= 0
__device__ unsigned g_bar_count = 0;
__device__ unsigned g_bar_gen = 0;

// ---------------- packed f32x2 helpers ----------------
__device__ __forceinline__ u64 fma2(u64 a, u64 b, u64 c) {
    u64 d;
    asm("fma.rn.f32x2 %0, %1, %2, %3;" : "=l"(d) : "l"(a), "l"(b), "l"(c));
    return d;
}
__device__ __forceinline__ u64 add2(u64 a, u64 b) {
    u64 d;
    asm("add.rn.f32x2 %0, %1, %2;" : "=l"(d) : "l"(a), "l"(b));
    return d;
}
__device__ __forceinline__ u64 pack2(float lo, float hi) {
    u64 r;
    asm("mov.b64 %0, {%1, %2};" : "=l"(r) : "f"(lo), "f"(hi));
    return r;
}
__device__ __forceinline__ void unpack2(u64 v, float& lo, float& hi) {
    asm("mov.b64 {%0, %1}, %2;" : "=f"(lo), "=f"(hi) : "l"(v));
}
__device__ __forceinline__ u64 relu2(u64 y) {
    float lo, hi;
    unpack2(y, lo, hi);
    lo = fmaxf(lo, 0.f);
    hi = fmaxf(hi, 0.f);
    return pack2(lo, hi);
}

// ---------------- grid-wide barrier (sense via generation counter) --------
// Reader-side __threadfence() (scope gpu >= cluster) emits CCTL.IVALL,
// invalidating stale L1D lines -> plain loads after the barrier are coherent.
__device__ __forceinline__ void grid_sync() {
    __syncthreads();
    if (threadIdx.x == 0) {
        unsigned gen = *((volatile unsigned*)&g_bar_gen);
        __threadfence();                       // release this block's writes
        if (atomicAdd(&g_bar_count, 1u) == NB - 1u) {
            g_bar_count = 0;
            __threadfence();
            atomicAdd(&g_bar_gen, 1u);
        } else {
            while (*((volatile unsigned*)&g_bar_gen) == gen) { __nanosleep(32); }
        }
        __threadfence();                       // acquire + L1 invalidate
    }
    __syncthreads();
}

// ---------------- the one kernel ----------------
__global__ void __launch_bounds__(256, 2) fused_kernel(
    const float* __restrict__ xv,  const float* __restrict__ W,
    const float* __restrict__ t1w, const float* __restrict__ t1b,
    const float* __restrict__ t2w, const float* __restrict__ t2b,
    const float* __restrict__ t3w, const float* __restrict__ t3b,
    const float* __restrict__ t4w, const float* __restrict__ t4b,
    const float* __restrict__ t5w, const float* __restrict__ t5b,
    const float* __restrict__ t6w, const float* __restrict__ t6b,
    const float* __restrict__ t7w, const float* __restrict__ t7b,
    float* __restrict__ out)
{
    __shared__ __align__(16) char smem_raw[26 * 1024 + 128];
    int tid = threadIdx.x;
    int blk = blockIdx.x;
    int e = tid & 63;
    int q = tid >> 6;           // 0..3

    // ===================== Phase A: setup =====================
    // g_base = xv@t1w + t1b + t3b (blocks 0..249, 8 rows each); init flags.
    {
        float* s1w = (float*)smem_raw;                     // 16 KB
        float (*sx)[EV] = (float(*)[EV])(smem_raw + 16384); // 2 KB
        if (blk < 250) {
            int j0 = blk * 8;
            for (int i = tid; i < EV * EV; i += 256) s1w[i] = t1w[i];
            for (int i = tid; i < 8 * EV; i += 256) {
                int jj = i >> 6, k = i & 63;
                sx[jj][k] = xv[(j0 + jj) * EV + k];
            }
            if (tid < 8) g_rowflag[j0 + tid] = 0;
            __syncthreads();
            #pragma unroll
            for (int p = 0; p < 2; p++) {
                int jj = q * 2 + p;
                float acc = t1b[e] + t3b[e];
                #pragma unroll
                for (int k = 0; k < EV; k++)
                    acc = fmaf(sx[jj][k], s1w[k * EV + e], acc);
                g_base[(j0 + jj) * EV + e] = acc;
            }
        } else if (blk == 250) {
            if (tid == 0) g_nz = 0;
        } else { // blk == 251: zero csum2 (4*64*8 = 2048 floats)
            float* cz = &g_csum2[0][0][0];
            #pragma unroll
            for (int r = 0; r < 8; r++) cz[tid + r * 256] = 0.f;
        }
    }
    grid_sync();   // barrier 1: base stores & zeroes before s3 atomics

    // ===================== Phase B: s3 =====================
    // r[b,e] = sum_a relu(W[a,b]*w4[e]+b4[e]); g_base += r_part @ t3w.
    {
        float (*sW)[32]     = (float(*)[32])(smem_raw);                // 1 KB
        float (*sR)[EV + 1] = (float(*)[EV + 1])(smem_raw + 1024);     // 8.3 KB
        float* s3w          = (float*)(smem_raw + 1024 + 8320);        // 16 KB

        int bl = tid & 31;
        int eg = tid >> 5;
        int bx = blk % 63;
        int by = blk / 63;
        int b0 = bx * 32;
        int a0 = by * 500;
        int a1 = a0 + 500;

        u64 w4p[4], b4p[4], acc[4];
        #pragma unroll
        for (int qq = 0; qq < 4; qq++) {
            int ee = eg * 8 + 2 * qq;
            w4p[qq] = pack2(t4w[ee], t4w[ee + 1]);
            b4p[qq] = pack2(t4b[ee], t4b[ee + 1]);
            acc[qq] = 0ull;
        }

        int lrow = tid >> 5;
        int lcol = b0 + bl;
        bool colok = (lcol < NV);

        int a = a0;
        for (; a + 8 <= a1; a += 8) {
            float wv = 0.f;
            if (colok) {
                wv = W[(a + lrow) * NV + lcol];
                if (wv <= 0.f) {
                    int p = atomicAdd(&g_nz, 1);
                    if (p < MAXZ) {
                        g_zpos[p].x = a + lrow;
                        g_zpos[p].y = lcol;
                        g_rowflag[a + lrow] = 1;
                    }
                }
            }
            sW[lrow][bl] = wv;
            __syncthreads();
            #pragma unroll
            for (int aa = 0; aa < 8; aa++) {
                float w = sW[aa][bl];
                u64 ww = pack2(w, w);
                #pragma unroll
                for (int qq = 0; qq < 4; qq++)
                    acc[qq] = add2(acc[qq], relu2(fma2(ww, w4p[qq], b4p[qq])));
            }
            __syncthreads();
        }
        if (a < a1) {   // tail: 500 = 62*8 + 4
            float wv = 0.f;
            if (colok && (a + lrow) < a1) {
                wv = W[(a + lrow) * NV + lcol];
                if (wv <= 0.f) {
                    int p = atomicAdd(&g_nz, 1);
                    if (p < MAXZ) {
                        g_zpos[p].x = a + lrow;
                        g_zpos[p].y = lcol;
                        g_rowflag[a + lrow] = 1;
                    }
                }
            }
            sW[lrow][bl] = wv;
            __syncthreads();
            int nt = a1 - a;
            for (int aa = 0; aa < nt; aa++) {
                float w = sW[aa][bl];
                u64 ww = pack2(w, w);
                #pragma unroll
                for (int qq = 0; qq < 4; qq++)
                    acc[qq] = add2(acc[qq], relu2(fma2(ww, w4p[qq], b4p[qq])));
            }
            __syncthreads();
        }

        #pragma unroll
        for (int qq = 0; qq < 4; qq++) {
            float lo, hi;
            unpack2(acc[qq], lo, hi);
            sR[bl][eg * 8 + 2 * qq]     = lo;
            sR[bl][eg * 8 + 2 * qq + 1] = hi;
        }
        for (int i = tid; i < EV * EV; i += 256) s3w[i] = t3w[i];
        __syncthreads();

        int grp = tid >> 6;
        #pragma unroll
        for (int p = 0; p < 8; p++) {
            int cr = grp * 8 + p;
            float s = 0.f;
            #pragma unroll
            for (int k = 0; k < EV; k++)
                s = fmaf(sR[cr][k], s3w[k * EV + e], s);
            int b = b0 + cr;
            if (b < NV) atomicAdd(&g_base[b * EV + e], s);
        }
    }
    grid_sync();   // barrier 2: g_base & zpos complete

    // ===================== Phase C: T-loop =====================
    {
        float* st2w = (float*)smem_raw;                         // 16 KB, persists
        float* ssc  = (float*)(smem_raw + 16384);               // 64
        float* ssv  = (float*)(smem_raw + 16640);               // 64
        float (*sscp)[EV] = (float(*)[EV])(smem_raw + 16896);   // 4x64

        for (int i = tid; i < EV * EV; i += 256) st2w[i] = t2w[i];
        // st2w consumed after the __syncthreads inside the loop below

        int nz0 = g_nz;
        if (nz0 > MAXZ) nz0 = MAXZ;
        int j0 = blk * 8;

        for (int t = 0; t < 4; t++) {
            // ---- v = csum_{t-1} @ t2w + t2b (all blocks, in shared) ----
            if (t == 0) {
                if (tid < EV) ssv[tid] = t2b[tid];
                __syncthreads();   // also covers first-use of st2w
            } else {
                if (tid < EV) {
                    float s = 0.f;
                    #pragma unroll
                    for (int s8 = 0; s8 < 8; s8++) s += g_csum2[t - 1][tid][s8];
                    ssc[tid] = s;
                }
                __syncthreads();
                float a = 0.f;
                #pragma unroll
                for (int k = 0; k < 16; k++) {
                    int kk = q * 16 + k;
                    a = fmaf(ssc[kk], st2w[kk * EV + e], a);
                }
                sscp[q][e] = a;
                __syncthreads();
                if (tid < EV)
                    ssv[tid] = sscp[0][tid] + sscp[1][tid] + sscp[2][tid]
                             + sscp[3][tid] + t2b[tid];
                __syncthreads();
            }

            // ---- mu rows (blocks 0..249) ----
            if (blk < 250) {
                int prev = (t - 1) & 1;
                float v = ssv[e];
                float csum = 0.f;
                #pragma unroll
                for (int p = 0; p < 2; p++) {
                    int j = j0 + q * 2 + p;
                    float corr = 0.f;
                    if (nz0 > 0 && t > 0 && g_rowflag[j]) {
                        for (int z = 0; z < nz0; z++) {
                            int2 zp = g_zpos[z];
                            if (zp.x == j) {
                                float a2 = 0.f;
                                for (int k = 0; k < EV; k++)
                                    a2 = fmaf(g_mu[prev][zp.y * EV + k],
                                              st2w[k * EV + e], a2);
                                corr += a2;
                            }
                        }
                    }
                    float m = fmaxf(g_base[j * EV + e] + v - corr, 0.f);
                    g_mu[t & 1][j * EV + e] = m;
                    csum += m;
                }
                sscp[q][e] = csum;
                __syncthreads();
                if (q == 0)
                    atomicAdd(&g_csum2[t][e][blk & 7],
                              sscp[0][e] + sscp[1][e] + sscp[2][e] + sscp[3][e]);
            }
            grid_sync();   // barriers 3..6
        }
    }

    // ===================== Phase D: final head =====================
    if (blk < 250) {
        float* s7w = (float*)smem_raw;                          // 16 KB
        float* scs = (float*)(smem_raw + 16384);                // 64
        float* sgv = (float*)(smem_raw + 16640);                // 64
        float (*smu)[EV] = (float(*)[EV])(smem_raw + 16896);    // 8x64 = 2 KB
        float (*swsum)[2] = (float(*)[2])(smem_raw + 18944);    // 8x2
        float* sgg = (float*)(smem_raw + 19072);

        int j0 = blk * 8;
        for (int i = tid; i < EV * EV; i += 256) s7w[i] = t7w[i];
        for (int i = tid; i < 8 * EV; i += 256) {
            int jj = i >> 6, k = i & 63;
            smu[jj][k] = g_mu[1][(j0 + jj) * EV + k];   // t=3 -> buffer 1
        }
        if (tid < EV) {
            float s = 0.f;
            #pragma unroll
            for (int s8 = 0; s8 < 8; s8++) s += g_csum2[3][tid][s8];
            scs[tid] = s;
        }
        __syncthreads();
        if (tid < EV) {
            float a = t6b[tid];
            #pragma unroll
            for (int k = 0; k < EV; k++)
                a = fmaf(scs[k], t6w[k * EV + tid], a);
            sgv[tid] = fmaxf(a, 0.f) * t5w[tid];
        }
        __syncthreads();
        if (tid == 0) {
            float gg = 0.f;
            #pragma unroll
            for (int k = 0; k < EV; k++) gg += sgv[k];
            sgg[0] = gg;
        }
        __syncthreads();

        float red[2];
        #pragma unroll
        for (int p = 0; p < 2; p++) {
            int jj = q * 2 + p;
            float acc = t7b[e];
            #pragma unroll
            for (int k = 0; k < EV; k++)
                acc = fmaf(smu[jj][k], s7w[k * EV + e], acc);
            float val = fmaxf(acc, 0.f) * t5w[EV + e];
            #pragma unroll
            for (int off = 16; off; off >>= 1)
                val += __shfl_xor_sync(0xffffffffu, val, off);
            red[p] = val;
        }
        int warp = tid >> 5, lane = tid & 31;
        if (lane == 0) {
            swsum[warp][0] = red[0];
            swsum[warp][1] = red[1];
        }
        __syncthreads();
        if (tid < 8) {
            int qq = tid >> 1, p = tid & 1;
            out[j0 + tid] = sgg[0] + t5b[0]
                          + swsum[2 * qq][p] + swsum[2 * qq + 1][p];
        }
    }
}

// ---------------- host launch ----------------
extern "C" void kernel_launch(void* const* d_in, const int* in_sizes, int n_in,
                              void* d_out, int out_size) {
    const float* xv  = (const float*)d_in[0];
    const float* W   = (const float*)d_in[1];
    const float* t1w = (const float*)d_in[2];
    const float* t1b = (const float*)d_in[3];
    const float* t2w = (const float*)d_in[4];
    const float* t2b = (const float*)d_in[5];
    const float* t3w = (const float*)d_in[6];
    const float* t3b = (const float*)d_in[7];
    const float* t4w = (const float*)d_in[8];
    const float* t4b = (const float*)d_in[9];
    const float* t5w = (const float*)d_in[10];
    const float* t5b = (const float*)d_in[11];
    const float* t6w = (const float*)d_in[12];
    const float* t6b = (const float*)d_in[13];
    const float* t7w = (const float*)d_in[14];
    const float* t7b = (const float*)d_in[15];
    float* out = (float*)d_out;

    fused_kernel<<<NB, 256>>>(xv, W, t1w, t1b, t2w, t2b, t3w, t3b,
                              t4w, t4b, t5w, t5b, t6w, t6b, t7w, t7b, out);
}

// round 8
// speedup vs baseline: 1.4743x; 1.1905x over previous
#include <cuda_runtime.h>

#define NV 2000
#define EV 64
#define MAXZ 4096
#define NB 148            // persistent blocks: exactly 1 per SM
#define NTHR 512
#define NROWBLK 143       // blocks doing row work (143*14 = 2002 >= 2000)
#define RPB 14            // rows per block in row-phases
#define NTILE 63          // 32-col tiles
#define CHPT 125          // 16-row chunks per tile (2000/16)
#define CHUNKS (NTILE * CHPT)   // 7875

typedef unsigned long long u64;

// ---------------- device scratch ----------------
__device__ float g_base[NV * EV];
__device__ float g_mu[2][NV * EV];
__device__ float g_csum2[4][EV][8];
__device__ int   g_nz;
__device__ int   g_rowflag[NV];
__device__ int2  g_zpos[MAXZ];
__device__ unsigned g_bar_count = 0;
__device__ unsigned g_bar_gen = 0;

// ---------------- packed f32x2 helpers ----------------
__device__ __forceinline__ u64 fma2(u64 a, u64 b, u64 c) {
    u64 d;
    asm("fma.rn.f32x2 %0, %1, %2, %3;" : "=l"(d) : "l"(a), "l"(b), "l"(c));
    return d;
}
__device__ __forceinline__ u64 add2(u64 a, u64 b) {
    u64 d;
    asm("add.rn.f32x2 %0, %1, %2;" : "=l"(d) : "l"(a), "l"(b));
    return d;
}
__device__ __forceinline__ u64 pack2(float lo, float hi) {
    u64 r;
    asm("mov.b64 %0, {%1, %2};" : "=l"(r) : "f"(lo), "f"(hi));
    return r;
}
__device__ __forceinline__ void unpack2(u64 v, float& lo, float& hi) {
    asm("mov.b64 {%0, %1}, %2;" : "=f"(lo), "=f"(hi) : "l"(v));
}
__device__ __forceinline__ u64 relu2(u64 y) {
    float lo, hi;
    unpack2(y, lo, hi);
    lo = fmaxf(lo, 0.f);
    hi = fmaxf(hi, 0.f);
    return pack2(lo, hi);
}

// ---------------- grid-wide barrier ----------------
__device__ __forceinline__ void grid_sync() {
    __syncthreads();
    if (threadIdx.x == 0) {
        unsigned gen = *((volatile unsigned*)&g_bar_gen);
        __threadfence();
        if (atomicAdd(&g_bar_count, 1u) == NB - 1u) {
            g_bar_count = 0;
            __threadfence();
            atomicAdd(&g_bar_gen, 1u);
        } else {
            while (*((volatile unsigned*)&g_bar_gen) == gen) { __nanosleep(32); }
        }
        __threadfence();
    }
    __syncthreads();
}

// ---------------- the one kernel ----------------
__global__ void __launch_bounds__(NTHR, 1) fused_kernel(
    const float* __restrict__ xv,  const float* __restrict__ W,
    const float* __restrict__ t1w, const float* __restrict__ t1b,
    const float* __restrict__ t2w, const float* __restrict__ t2b,
    const float* __restrict__ t3w, const float* __restrict__ t3b,
    const float* __restrict__ t4w, const float* __restrict__ t4b,
    const float* __restrict__ t5w, const float* __restrict__ t5b,
    const float* __restrict__ t6w, const float* __restrict__ t6b,
    const float* __restrict__ t7w, const float* __restrict__ t7b,
    float* __restrict__ out)
{
    __shared__ __align__(16) char smem_raw[30 * 1024];
    int tid = threadIdx.x;
    int blk = blockIdx.x;
    int e = tid & 63;
    int grp = tid >> 6;          // 0..7

    // ===================== Phase A: setup =====================
    {
        float* s1w = (float*)smem_raw;                       // 16 KB
        float (*sx)[EV] = (float(*)[EV])(smem_raw + 16384);  // 14x64
        if (blk < NROWBLK) {
            int j0 = blk * RPB;
            for (int i = tid; i < EV * EV; i += NTHR) s1w[i] = t1w[i];
            for (int i = tid; i < RPB * EV; i += NTHR) {
                int jj = i >> 6, k = i & 63;
                int j = j0 + jj;
                sx[jj][k] = (j < NV) ? xv[j * EV + k] : 0.f;
            }
            if (tid < RPB && j0 + tid < NV) g_rowflag[j0 + tid] = 0;
            __syncthreads();
            #pragma unroll
            for (int p = 0; p < 2; p++) {
                int jj = grp + p * 8;
                int j = j0 + jj;
                if (jj < RPB && j < NV) {
                    float acc = t1b[e] + t3b[e];
                    #pragma unroll
                    for (int k = 0; k < EV; k++)
                        acc = fmaf(sx[jj][k], s1w[k * EV + e], acc);
                    g_base[j * EV + e] = acc;
                }
            }
        } else if (blk == 143) {
            if (tid == 0) g_nz = 0;
        } else if (blk == 144) {
            float* cz = &g_csum2[0][0][0];
            #pragma unroll
            for (int r = 0; r < 4; r++) cz[tid + r * NTHR] = 0.f;
        }
    }
    grid_sync();   // barrier 1

    // ===================== Phase B: s3 =====================
    // flat queue of 7875 chunks (tile-major), double-buffered smem pipeline
    {
        float* s3w = (float*)smem_raw;                               // 16 KB
        float* sWb = (float*)(smem_raw + 16384);                     // 2 x 512
        float (*sR)[EV + 1] = (float(*)[EV + 1])(smem_raw + 16384 + 4096);

        for (int i = tid; i < EV * EV; i += NTHR) s3w[i] = t3w[i];

        int bl   = tid & 31;         // column within tile
        int eg   = tid >> 5;         // 0..15 (4 e's each)
        int lrow = tid >> 5;         // load row 0..15
        int e0 = eg * 4;
        u64 w4p0 = pack2(t4w[e0],     t4w[e0 + 1]);
        u64 w4p1 = pack2(t4w[e0 + 2], t4w[e0 + 3]);
        u64 b4p0 = pack2(t4b[e0],     t4b[e0 + 1]);
        u64 b4p1 = pack2(t4b[e0 + 2], t4b[e0 + 3]);

        long long c  = (long long)blk * CHUNKS / NB;
        long long cE = (long long)(blk + 1) * CHUNKS / NB;

        while (c < cE) {
            int tile = (int)(c / CHPT);
            int ch0  = (int)(c % CHPT);
            int nch  = CHPT - ch0;
            if (nch > (int)(cE - c)) nch = (int)(cE - c);
            int b0 = tile * 32;
            int lcol = b0 + bl;
            bool colok = (lcol < NV);

            u64 acc0 = 0ull, acc1 = 0ull;

            // prefetch first chunk
            {
                int a = (ch0) * 16 + lrow;
                float wv = 0.f;
                if (colok) {
                    wv = W[a * NV + lcol];
                    if (wv <= 0.f) {
                        int p = atomicAdd(&g_nz, 1);
                        if (p < MAXZ) {
                            g_zpos[p].x = a;
                            g_zpos[p].y = lcol;
                            g_rowflag[a] = 1;
                        }
                    }
                }
                sWb[lrow * 32 + bl] = wv;
            }
            __syncthreads();

            int buf = 0;
            for (int i = 0; i < nch; i++) {
                float wn = 0.f;
                if (i + 1 < nch) {       // issue next LDG early
                    int a = (ch0 + i + 1) * 16 + lrow;
                    if (colok) {
                        wn = W[a * NV + lcol];
                        if (wn <= 0.f) {
                            int p = atomicAdd(&g_nz, 1);
                            if (p < MAXZ) {
                                g_zpos[p].x = a;
                                g_zpos[p].y = lcol;
                                g_rowflag[a] = 1;
                            }
                        }
                    }
                }
                const float* sb = sWb + buf * 512;
                #pragma unroll
                for (int aa = 0; aa < 16; aa++) {
                    float w = sb[aa * 32 + bl];
                    u64 ww = pack2(w, w);
                    acc0 = add2(acc0, relu2(fma2(ww, w4p0, b4p0)));
                    acc1 = add2(acc1, relu2(fma2(ww, w4p1, b4p1)));
                }
                if (i + 1 < nch)
                    sWb[(buf ^ 1) * 512 + lrow * 32 + bl] = wn;
                __syncthreads();
                buf ^= 1;
            }

            // epilogue: sR = partial r ; g_base += sR @ t3w
            {
                float l0, h0, l1, h1;
                unpack2(acc0, l0, h0);
                unpack2(acc1, l1, h1);
                sR[bl][e0]     = l0;
                sR[bl][e0 + 1] = h0;
                sR[bl][e0 + 2] = l1;
                sR[bl][e0 + 3] = h1;
                __syncthreads();
                int f = tid & 63;
                int g8 = tid >> 6;     // 0..7
                #pragma unroll
                for (int p = 0; p < 4; p++) {
                    int cr = g8 * 4 + p;
                    float s = 0.f;
                    #pragma unroll
                    for (int k = 0; k < EV; k++)
                        s = fmaf(sR[cr][k], s3w[k * EV + f], s);
                    int b = b0 + cr;
                    if (b < NV) atomicAdd(&g_base[b * EV + f], s);
                }
                __syncthreads();   // sR/sWb safe for next segment
            }
            c += nch;
        }
    }
    grid_sync();   // barrier 2

    // ===================== Phase C: T-loop =====================
    {
        float* st2w = (float*)smem_raw;                          // 16 KB
        float* ssc  = (float*)(smem_raw + 16384);                // 64
        float* ssv  = (float*)(smem_raw + 16640);                // 64
        float (*sscp)[EV] = (float(*)[EV])(smem_raw + 16896);    // 8x64

        for (int i = tid; i < EV * EV; i += NTHR) st2w[i] = t2w[i];

        int nz0 = g_nz;
        if (nz0 > MAXZ) nz0 = MAXZ;
        int j0 = blk * RPB;

        for (int t = 0; t < 4; t++) {
            if (t == 0) {
                if (tid < EV) ssv[tid] = t2b[tid];
                __syncthreads();
            } else {
                if (tid < EV) {
                    float s = 0.f;
                    #pragma unroll
                    for (int s8 = 0; s8 < 8; s8++) s += g_csum2[t - 1][tid][s8];
                    ssc[tid] = s;
                }
                __syncthreads();
                float a = 0.f;
                #pragma unroll
                for (int k = 0; k < 8; k++) {
                    int kk = grp * 8 + k;
                    a = fmaf(ssc[kk], st2w[kk * EV + e], a);
                }
                sscp[grp][e] = a;
                __syncthreads();
                if (tid < EV) {
                    float s = t2b[tid];
                    #pragma unroll
                    for (int s8 = 0; s8 < 8; s8++) s += sscp[s8][tid];
                    ssv[tid] = s;
                }
                __syncthreads();
            }

            float csum = 0.f;
            if (blk < NROWBLK) {
                int prev = (t - 1) & 1;
                float v = ssv[e];
                #pragma unroll
                for (int p = 0; p < 2; p++) {
                    int jj = grp + p * 8;
                    int j = j0 + jj;
                    if (jj < RPB && j < NV) {
                        float corr = 0.f;
                        if (nz0 > 0 && t > 0 && g_rowflag[j]) {
                            for (int z = 0; z < nz0; z++) {
                                int2 zp = g_zpos[z];
                                if (zp.x == j) {
                                    float a2 = 0.f;
                                    for (int k = 0; k < EV; k++)
                                        a2 = fmaf(g_mu[prev][zp.y * EV + k],
                                                  st2w[k * EV + e], a2);
                                    corr += a2;
                                }
                            }
                        }
                        float m = fmaxf(g_base[j * EV + e] + v - corr, 0.f);
                        g_mu[t & 1][j * EV + e] = m;
                        csum += m;
                    }
                }
            }
            sscp[grp][e] = csum;
            __syncthreads();
            if (tid < EV && blk < NROWBLK) {
                float s = 0.f;
                #pragma unroll
                for (int s8 = 0; s8 < 8; s8++) s += sscp[s8][tid];
                atomicAdd(&g_csum2[t][tid][blk & 7], s);
            }
            grid_sync();   // barriers 3..6
        }
    }

    // ===================== Phase D: final head =====================
    if (blk < NROWBLK) {
        float* s7w = (float*)smem_raw;                           // 16 KB
        float* scs = (float*)(smem_raw + 16384);                 // 64
        float* sgv = (float*)(smem_raw + 16640);                 // 64
        float (*smu)[EV] = (float(*)[EV])(smem_raw + 16896);     // 16x64
        float (*swsum)[2] = (float(*)[2])(smem_raw + 16896 + 4096); // 16x2
        float* sgg = (float*)(smem_raw + 16896 + 4096 + 128);

        int j0 = blk * RPB;
        for (int i = tid; i < EV * EV; i += NTHR) s7w[i] = t7w[i];
        for (int i = tid; i < 16 * EV; i += NTHR) {
            int jj = i >> 6, k = i & 63;
            int j = j0 + jj;
            smu[jj][k] = (jj < RPB && j < NV) ? g_mu[1][j * EV + k] : 0.f;
        }
        if (tid < EV) {
            float s = 0.f;
            #pragma unroll
            for (int s8 = 0; s8 < 8; s8++) s += g_csum2[3][tid][s8];
            scs[tid] = s;
        }
        __syncthreads();
        if (tid < EV) {
            float a = t6b[tid];
            #pragma unroll
            for (int k = 0; k < EV; k++)
                a = fmaf(scs[k], t6w[k * EV + tid], a);
            sgv[tid] = fmaxf(a, 0.f) * t5w[tid];
        }
        __syncthreads();
        if (tid == 0) {
            float gg = 0.f;
            #pragma unroll
            for (int k = 0; k < EV; k++) gg += sgv[k];
            sgg[0] = gg;
        }
        __syncthreads();

        float red[2];
        #pragma unroll
        for (int p = 0; p < 2; p++) {
            int jj = grp + p * 8;
            float acc = t7b[e];
            #pragma unroll
            for (int k = 0; k < EV; k++)
                acc = fmaf(smu[jj][k], s7w[k * EV + e], acc);
            float val = fmaxf(acc, 0.f) * t5w[EV + e];
            #pragma unroll
            for (int off = 16; off; off >>= 1)
                val += __shfl_xor_sync(0xffffffffu, val, off);
            red[p] = val;
        }
        int warp = tid >> 5, lane = tid & 31;
        if (lane == 0) {
            swsum[warp][0] = red[0];
            swsum[warp][1] = red[1];
        }
        __syncthreads();
        if (tid < 16) {
            int g8 = tid & 7, p = tid >> 3;
            int jj = g8 + p * 8;
            int j = j0 + jj;
            if (jj < RPB && j < NV)
                out[j] = sgg[0] + t5b[0]
                       + swsum[2 * g8][p] + swsum[2 * g8 + 1][p];
        }
    }
}

// ---------------- host launch ----------------
extern "C" void kernel_launch(void* const* d_in, const int* in_sizes, int n_in,
                              void* d_out, int out_size) {
    const float* xv  = (const float*)d_in[0];
    const float* W   = (const float*)d_in[1];
    const float* t1w = (const float*)d_in[2];
    const float* t1b = (const float*)d_in[3];
    const float* t2w = (const float*)d_in[4];
    const float* t2b = (const float*)d_in[5];
    const float* t3w = (const float*)d_in[6];
    const float* t3b = (const float*)d_in[7];
    const float* t4w = (const float*)d_in[8];
    const float* t4b = (const float*)d_in[9];
    const float* t5w = (const float*)d_in[10];
    const float* t5b = (const float*)d_in[11];
    const float* t6w = (const float*)d_in[12];
    const float* t6b = (const float*)d_in[13];
    const float* t7w = (const float*)d_in[14];
    const float* t7b = (const float*)d_in[15];
    float* out = (float*)d_out;

    fused_kernel<<<NB, NTHR>>>(xv, W, t1w, t1b, t2w, t2b, t3w, t3b,
                               t4w, t4b, t5w, t5b, t6w, t6b, t7w, t7b, out);
}

// round 9
// speedup vs baseline: 1.5901x; 1.0785x over previous
#include <cuda_runtime.h>

#define NV 2000
#define EV 64
#define MAXZ 4096
#define NB 148            // persistent blocks: exactly 1 per SM
#define NTHR 512
#define NROWBLK 143       // blocks doing row work (143*14 >= 2000)
#define RPB 14
#define TILEC 64          // columns per tile
#define NTILE 32          // ceil(2000/64)
#define CHPT 125          // 16-row chunks per tile
#define CHUNKS (NTILE * CHPT)   // 4000

typedef unsigned long long u64;

// ---------------- device scratch ----------------
__device__ float g_base[NV * EV];
__device__ float g_mu[2][NV * EV];
__device__ float g_csum2[4][EV][8];
__device__ int   g_nz;
__device__ int   g_rowflag[NV];
__device__ int2  g_zpos[MAXZ];
__device__ unsigned g_bar_count = 0;
__device__ unsigned g_bar_gen = 0;

// ---------------- packed f32x2 helpers ----------------
__device__ __forceinline__ u64 fma2(u64 a, u64 b, u64 c) {
    u64 d;
    asm("fma.rn.f32x2 %0, %1, %2, %3;" : "=l"(d) : "l"(a), "l"(b), "l"(c));
    return d;
}
__device__ __forceinline__ u64 add2(u64 a, u64 b) {
    u64 d;
    asm("add.rn.f32x2 %0, %1, %2;" : "=l"(d) : "l"(a), "l"(b));
    return d;
}
__device__ __forceinline__ u64 pack2(float lo, float hi) {
    u64 r;
    asm("mov.b64 %0, {%1, %2};" : "=l"(r) : "f"(lo), "f"(hi));
    return r;
}
__device__ __forceinline__ void unpack2(u64 v, float& lo, float& hi) {
    asm("mov.b64 {%0, %1}, %2;" : "=f"(lo), "=f"(hi) : "l"(v));
}
__device__ __forceinline__ u64 relu2(u64 y) {
    float lo, hi;
    unpack2(y, lo, hi);
    lo = fmaxf(lo, 0.f);
    hi = fmaxf(hi, 0.f);
    return pack2(lo, hi);
}

__device__ __forceinline__ void record_zero(int a, int b) {
    int p = atomicAdd(&g_nz, 1);
    if (p < MAXZ) {
        g_zpos[p].x = a;
        g_zpos[p].y = b;
        g_rowflag[a] = 1;
    }
}

// ---------------- grid-wide barrier ----------------
__device__ __forceinline__ void grid_sync() {
    __syncthreads();
    if (threadIdx.x == 0) {
        unsigned gen = *((volatile unsigned*)&g_bar_gen);
        __threadfence();
        if (atomicAdd(&g_bar_count, 1u) == NB - 1u) {
            g_bar_count = 0;
            __threadfence();
            atomicAdd(&g_bar_gen, 1u);
        } else {
            while (*((volatile unsigned*)&g_bar_gen) == gen) { __nanosleep(32); }
        }
        __threadfence();
    }
    __syncthreads();
}

// ---------------- the one kernel ----------------
__global__ void __launch_bounds__(NTHR, 1) fused_kernel(
    const float* __restrict__ xv,  const float* __restrict__ W,
    const float* __restrict__ t1w, const float* __restrict__ t1b,
    const float* __restrict__ t2w, const float* __restrict__ t2b,
    const float* __restrict__ t3w, const float* __restrict__ t3b,
    const float* __restrict__ t4w, const float* __restrict__ t4b,
    const float* __restrict__ t5w, const float* __restrict__ t5b,
    const float* __restrict__ t6w, const float* __restrict__ t6b,
    const float* __restrict__ t7w, const float* __restrict__ t7b,
    float* __restrict__ out)
{
    __shared__ __align__(16) char smem_raw[45440];
    int tid = threadIdx.x;
    int blk = blockIdx.x;
    int e = tid & 63;
    int grp = tid >> 6;          // 0..7

    // ===================== Phase A: setup =====================
    {
        float* s1w = (float*)smem_raw;
        float (*sx)[EV] = (float(*)[EV])(smem_raw + 16384);
        if (blk < NROWBLK) {
            int j0 = blk * RPB;
            for (int i = tid; i < EV * EV; i += NTHR) s1w[i] = t1w[i];
            for (int i = tid; i < RPB * EV; i += NTHR) {
                int jj = i >> 6, k = i & 63;
                int j = j0 + jj;
                sx[jj][k] = (j < NV) ? xv[j * EV + k] : 0.f;
            }
            if (tid < RPB && j0 + tid < NV) g_rowflag[j0 + tid] = 0;
            __syncthreads();
            #pragma unroll
            for (int p = 0; p < 2; p++) {
                int jj = grp + p * 8;
                int j = j0 + jj;
                if (jj < RPB && j < NV) {
                    float acc = t1b[e] + t3b[e];
                    #pragma unroll
                    for (int k = 0; k < EV; k++)
                        acc = fmaf(sx[jj][k], s1w[k * EV + e], acc);
                    g_base[j * EV + e] = acc;
                }
            }
        } else if (blk == 143) {
            if (tid == 0) g_nz = 0;
        } else if (blk == 144) {
            float* cz = &g_csum2[0][0][0];
            #pragma unroll
            for (int r = 0; r < 4; r++) cz[tid + r * NTHR] = 0.f;
        }
    }
    grid_sync();   // barrier 1

    // ===================== Phase B: s3 with cp.async pipeline =====================
    {
        float* s3w = (float*)smem_raw;                        // 16 KB
        float* stg = (float*)(smem_raw + 16384);              // 3 x 4 KB stages
        float* sR  = (float*)(smem_raw + 16384 + 12288);      // 64 x 65 floats

        for (int i = tid; i < EV * EV; i += NTHR) s3w[i] = t3w[i];

        int bl = tid & 63;          // column within tile
        int eg = tid >> 6;          // 0..7, constant per warp
        int e0 = eg * 8;
        u64 w4p[4], b4p[4], acc[4];
        #pragma unroll
        for (int qq = 0; qq < 4; qq++) {
            w4p[qq] = pack2(t4w[e0 + 2 * qq], t4w[e0 + 2 * qq + 1]);
            b4p[qq] = pack2(t4b[e0 + 2 * qq], t4b[e0 + 2 * qq + 1]);
            acc[qq] = 0ull;
        }

        int c0 = (int)((long long)blk * CHUNKS / NB);
        int cE = (int)((long long)(blk + 1) * CHUNKS / NB);

        // issue a chunk's 16x64 tile via cp.async (threads 0..255, 16B each)
        auto issue = [&](int c) {
            if (c < cE && tid < 256) {
                int tile = c / CHPT, ch = c % CHPT;
                int row = tid >> 4;     // 0..15
                int g   = tid & 15;     // 16B group within row
                int col0 = tile * TILEC + g * 4;
                long long a = (long long)(ch * 16 + row);
                int sbytes = (col0 + 4 <= NV) ? 16 : 0;   // NV%4==0 -> full or empty
                const float* src = W + a * NV + (sbytes ? col0 : 0);
                unsigned dst = (unsigned)__cvta_generic_to_shared(
                    stg + (c % 3) * 1024 + row * 64 + g * 4);
                asm volatile("cp.async.cg.shared.global [%0], [%1], 16, %2;"
                             :: "r"(dst), "l"(src), "r"(sbytes) : "memory");
            }
            asm volatile("cp.async.commit_group;" ::: "memory");
        };

        issue(c0);
        issue(c0 + 1);

        for (int c = c0; c < cE; c++) {
            asm volatile("cp.async.wait_group 1;" ::: "memory");
            __syncthreads();             // chunk c visible; stage (c+2)%3 free
            issue(c + 2);

            const float* sb = stg + (c % 3) * 1024;
            int tile = c / CHPT, ch = c % CHPT;
            int b0 = tile * TILEC;

            // zero-detect from smem: 2 values per thread, exact coverage
            {
                int idx = tid * 2;
                float v0 = sb[idx], v1 = sb[idx + 1];
                if (v0 <= 0.f || v1 <= 0.f) {
                    int row = idx >> 6, col = idx & 63;
                    int a = ch * 16 + row;
                    if (v0 <= 0.f && b0 + col < NV)     record_zero(a, b0 + col);
                    if (v1 <= 0.f && b0 + col + 1 < NV) record_zero(a, b0 + col + 1);
                }
            }

            #pragma unroll
            for (int aa = 0; aa < 16; aa++) {
                float w = sb[aa * 64 + bl];
                u64 ww = pack2(w, w);
                acc[0] = add2(acc[0], relu2(fma2(ww, w4p[0], b4p[0])));
                acc[1] = add2(acc[1], relu2(fma2(ww, w4p[1], b4p[1])));
                acc[2] = add2(acc[2], relu2(fma2(ww, w4p[2], b4p[2])));
                acc[3] = add2(acc[3], relu2(fma2(ww, w4p[3], b4p[3])));
            }

            // tile-boundary epilogue: g_base[b0+cr, f] += sR[cr] @ t3w
            if (c + 1 == cE || (c + 1) % CHPT == 0) {
                #pragma unroll
                for (int qq = 0; qq < 4; qq++) {
                    float lo, hi;
                    unpack2(acc[qq], lo, hi);
                    sR[bl * 65 + e0 + 2 * qq]     = lo;
                    sR[bl * 65 + e0 + 2 * qq + 1] = hi;
                    acc[qq] = 0ull;
                }
                __syncthreads();
                int f = tid & 63;
                int g8 = tid >> 6;
                #pragma unroll
                for (int p = 0; p < 8; p++) {
                    int cr = g8 * 8 + p;
                    float s = 0.f;
                    #pragma unroll
                    for (int k = 0; k < EV; k++)
                        s = fmaf(sR[cr * 65 + k], s3w[k * EV + f], s);
                    int b = b0 + cr;
                    if (b < NV) atomicAdd(&g_base[b * EV + f], s);
                }
                __syncthreads();
            }
        }
        asm volatile("cp.async.wait_group 0;" ::: "memory");
    }
    grid_sync();   // barrier 2

    // ===================== Phase C: T-loop =====================
    {
        float* st2w = (float*)smem_raw;
        float* ssc  = (float*)(smem_raw + 16384);
        float* ssv  = (float*)(smem_raw + 16640);
        float (*sscp)[EV] = (float(*)[EV])(smem_raw + 16896);

        for (int i = tid; i < EV * EV; i += NTHR) st2w[i] = t2w[i];

        int nz0 = g_nz;
        if (nz0 > MAXZ) nz0 = MAXZ;
        int j0 = blk * RPB;

        for (int t = 0; t < 4; t++) {
            if (t == 0) {
                if (tid < EV) ssv[tid] = t2b[tid];
                __syncthreads();
            } else {
                if (tid < EV) {
                    float s = 0.f;
                    #pragma unroll
                    for (int s8 = 0; s8 < 8; s8++) s += g_csum2[t - 1][tid][s8];
                    ssc[tid] = s;
                }
                __syncthreads();
                float a = 0.f;
                #pragma unroll
                for (int k = 0; k < 8; k++) {
                    int kk = grp * 8 + k;
                    a = fmaf(ssc[kk], st2w[kk * EV + e], a);
                }
                sscp[grp][e] = a;
                __syncthreads();
                if (tid < EV) {
                    float s = t2b[tid];
                    #pragma unroll
                    for (int s8 = 0; s8 < 8; s8++) s += sscp[s8][tid];
                    ssv[tid] = s;
                }
                __syncthreads();
            }

            float csum = 0.f;
            if (blk < NROWBLK) {
                int prev = (t - 1) & 1;
                float v = ssv[e];
                #pragma unroll
                for (int p = 0; p < 2; p++) {
                    int jj = grp + p * 8;
                    int j = j0 + jj;
                    if (jj < RPB && j < NV) {
                        float corr = 0.f;
                        if (nz0 > 0 && t > 0 && g_rowflag[j]) {
                            for (int z = 0; z < nz0; z++) {
                                int2 zp = g_zpos[z];
                                if (zp.x == j) {
                                    float a2 = 0.f;
                                    for (int k = 0; k < EV; k++)
                                        a2 = fmaf(g_mu[prev][zp.y * EV + k],
                                                  st2w[k * EV + e], a2);
                                    corr += a2;
                                }
                            }
                        }
                        float m = fmaxf(g_base[j * EV + e] + v - corr, 0.f);
                        g_mu[t & 1][j * EV + e] = m;
                        csum += m;
                    }
                }
            }
            sscp[grp][e] = csum;
            __syncthreads();
            if (tid < EV && blk < NROWBLK) {
                float s = 0.f;
                #pragma unroll
                for (int s8 = 0; s8 < 8; s8++) s += sscp[s8][tid];
                atomicAdd(&g_csum2[t][tid][blk & 7], s);
            }
            grid_sync();   // barriers 3..6
        }
    }

    // ===================== Phase D: final head =====================
    if (blk < NROWBLK) {
        float* s7w = (float*)smem_raw;
        float* scs = (float*)(smem_raw + 16384);
        float* sgv = (float*)(smem_raw + 16640);
        float (*smu)[EV] = (float(*)[EV])(smem_raw + 16896);
        float (*swsum)[2] = (float(*)[2])(smem_raw + 16896 + 4096);
        float* sgg = (float*)(smem_raw + 16896 + 4096 + 128);

        int j0 = blk * RPB;
        for (int i = tid; i < EV * EV; i += NTHR) s7w[i] = t7w[i];
        for (int i = tid; i < 16 * EV; i += NTHR) {
            int jj = i >> 6, k = i & 63;
            int j = j0 + jj;
            smu[jj][k] = (jj < RPB && j < NV) ? g_mu[1][j * EV + k] : 0.f;
        }
        if (tid < EV) {
            float s = 0.f;
            #pragma unroll
            for (int s8 = 0; s8 < 8; s8++) s += g_csum2[3][tid][s8];
            scs[tid] = s;
        }
        __syncthreads();
        if (tid < EV) {
            float a = t6b[tid];
            #pragma unroll
            for (int k = 0; k < EV; k++)
                a = fmaf(scs[k], t6w[k * EV + tid], a);
            sgv[tid] = fmaxf(a, 0.f) * t5w[tid];
        }
        __syncthreads();
        if (tid == 0) {
            float gg = 0.f;
            #pragma unroll
            for (int k = 0; k < EV; k++) gg += sgv[k];
            sgg[0] = gg;
        }
        __syncthreads();

        float red[2];
        #pragma unroll
        for (int p = 0; p < 2; p++) {
            int jj = grp + p * 8;
            float acc = t7b[e];
            #pragma unroll
            for (int k = 0; k < EV; k++)
                acc = fmaf(smu[jj][k], s7w[k * EV + e], acc);
            float val = fmaxf(acc, 0.f) * t5w[EV + e];
            #pragma unroll
            for (int off = 16; off; off >>= 1)
                val += __shfl_xor_sync(0xffffffffu, val, off);
            red[p] = val;
        }
        int warp = tid >> 5, lane = tid & 31;
        if (lane == 0) {
            swsum[warp][0] = red[0];
            swsum[warp][1] = red[1];
        }
        __syncthreads();
        if (tid < 16) {
            int g8 = tid & 7, p = tid >> 3;
            int jj = g8 + p * 8;
            int j = j0 + jj;
            if (jj < RPB && j < NV)
                out[j] = sgg[0] + t5b[0]
                       + swsum[2 * g8][p] + swsum[2 * g8 + 1][p];
        }
    }
}

// ---------------- host launch ----------------
extern "C" void kernel_launch(void* const* d_in, const int* in_sizes, int n_in,
                              void* d_out, int out_size) {
    const float* xv  = (const float*)d_in[0];
    const float* W   = (const float*)d_in[1];
    const float* t1w = (const float*)d_in[2];
    const float* t1b = (const float*)d_in[3];
    const float* t2w = (const float*)d_in[4];
    const float* t2b = (const float*)d_in[5];
    const float* t3w = (const float*)d_in[6];
    const float* t3b = (const float*)d_in[7];
    const float* t4w = (const float*)d_in[8];
    const float* t4b = (const float*)d_in[9];
    const float* t5w = (const float*)d_in[10];
    const float* t5b = (const float*)d_in[11];
    const float* t6w = (const float*)d_in[12];
    const float* t6b = (const float*)d_in[13];
    const float* t7w = (const float*)d_in[14];
    const float* t7b = (const float*)d_in[15];
    float* out = (float*)d_out;

    fused_kernel<<<NB, NTHR>>>(xv, W, t1w, t1b, t2w, t2b, t3w, t3b,
                               t4w, t4b, t5w, t5b, t6w, t6b, t7w, t7b, out);
}